// round 14
// baseline (speedup 1.0000x reference)
#include <cuda_runtime.h>
#include <cuda_fp16.h>
#include <cstdint>
#include <math.h>

// ---------------- problem constants ----------------
#define BATCH 8
#define CIN   64
#define COUT  64
#define SDIM  512
#define HH    256
#define WW    256
#define TAPS  9

#define CONV_SCALE (1.0f / 24.0f)
#define MOD_SCALE  (0.04419417382415922f)
#define EPSV       (1e-8f)

// ---------------- helpers ----------------
__device__ __forceinline__ uint32_t smem_u32(const void* p) {
    uint32_t a;
    asm("{ .reg .u64 t; cvta.to.shared.u64 t, %1; cvt.u32.u64 %0, t; }" : "=r"(a) : "l"(p));
    return a;
}
__device__ __forceinline__ void ldsm4(uint32_t (&r)[4], uint32_t addr) {
    asm volatile("ldmatrix.sync.aligned.m8n8.x4.shared.b16 {%0,%1,%2,%3}, [%4];"
                 : "=r"(r[0]), "=r"(r[1]), "=r"(r[2]), "=r"(r[3]) : "r"(addr));
}
__device__ __forceinline__ void mma16816(float (&c)[4], const uint32_t (&a)[4],
                                         const uint32_t b0, const uint32_t b1) {
    asm volatile(
        "mma.sync.aligned.m16n8k16.row.col.f32.f16.f16.f32 "
        "{%0,%1,%2,%3}, {%4,%5,%6,%7}, {%8,%9}, {%0,%1,%2,%3};"
        : "+f"(c[0]), "+f"(c[1]), "+f"(c[2]), "+f"(c[3])
        : "r"(a[0]), "r"(a[1]), "r"(a[2]), "r"(a[3]), "r"(b0), "r"(b1));
}
__device__ __forceinline__ void cpasync16(uint32_t dst, const void* src) {
    asm volatile("cp.async.cg.shared.global [%0], [%1], 16;" :: "r"(dst), "l"(src) : "memory");
}
__device__ __forceinline__ void cpcommit() { asm volatile("cp.async.commit_group;" ::: "memory"); }
__device__ __forceinline__ void cpwait0()  { asm volatile("cp.async.wait_group 0;" ::: "memory"); }

__device__ __forceinline__ uint32_t sw128(uint32_t o) { return o ^ ((o >> 3) & 0x70u); }

// ---------------- SMEM layout ----------------
#define W_OFF      0u
#define W_BYTES    73728u
#define RING_OFF   73728u
#define ROW_STRIDE 16640u                        // 130 px x 128B
#define STAGE_OFF  (RING_OFF + 6u * ROW_STRIDE)  // 173568
#define STAGE_W    136                           // fp32 words per ci row
#define SMEM_TOTAL (STAGE_OFF + 64u * STAGE_W * 4u)   // 208384

#define NCTA       148

// ---- in-CTA demodulated weight computation, register-isolated -------------
// NOINLINE: keeps its register pressure out of the persistent mainloop's
// allocation (R13 inlined this and spilled the whole kernel to 255 regs).
// Two-pass over wgt (sumsq, then recompute+store) to keep the callee lean.
__device__ __noinline__ void compute_weights(char* smem, int bb,
                                             const float* __restrict__ style,
                                             const float* __restrict__ mw,
                                             const float* __restrict__ mbias,
                                             const float* __restrict__ wgt) {
    const int tid  = threadIdx.x;
    const int wid  = tid >> 5;
    const int lane = tid & 31;
    float* sdot = (float*)(smem + STAGE_OFF);    // stage buffer as scratch

    // phase 1: sdot[ci] = MOD_SCALE * <style_bb, mw_ci> + mbias[ci]
    {
        int ci = tid >> 2, qq = tid & 3;
        const float4* sp = (const float4*)(style + (size_t)bb * SDIM) + qq * 32;
        const float4* wp = (const float4*)(mw + (size_t)ci * SDIM) + qq * 32;
        float sum = 0.f;
        #pragma unroll 8
        for (int it = 0; it < 32; it++) {
            float4 s4 = sp[it];
            float4 w4 = wp[it];
            sum += s4.x * w4.x + s4.y * w4.y + s4.z * w4.z + s4.w * w4.w;
        }
        sum += __shfl_xor_sync(0xFFFFFFFFu, sum, 1);
        sum += __shfl_xor_sync(0xFFFFFFFFu, sum, 2);
        if (qq == 0) sdot[ci] = sum * MOD_SCALE + mbias[ci];
    }
    __syncthreads();

    // phase 2: warp w owns co = 8w..8w+7
    #pragma unroll 1
    for (int i = 0; i < 8; i++) {
        int co = wid * 8 + i;
        const float* wrow = wgt + (size_t)co * 576;
        float sumsq = 0.f;
        #pragma unroll 1
        for (int k = 0; k < 18; k++) {
            int e  = lane + 32 * k;
            int ci = e / 9;
            float v = CONV_SCALE * wrow[e] * sdot[ci];
            sumsq += v * v;
        }
        #pragma unroll
        for (int off = 16; off > 0; off >>= 1)
            sumsq += __shfl_xor_sync(0xFFFFFFFFu, sumsq, off);
        float dm = rsqrtf(sumsq + EPSV);
        #pragma unroll 1
        for (int k = 0; k < 18; k++) {
            int e   = lane + 32 * k;
            int ci  = e / 9;
            int tap = e - ci * 9;
            float v = CONV_SCALE * wrow[e] * sdot[ci];   // L1 hit (2nd read)
            uint32_t o = ((uint32_t)(tap * 64 + co)) * 128u + (uint32_t)ci * 2u;
            *(__half*)(smem + W_OFF + sw128(o)) = __float2half_rn(v * dm);
        }
    }
    __syncthreads();
}

// ---------------- single persistent kernel ---------------------------------
// Work unit = chunk (xh, y4chunk, b): 128px x 64co x 4 rows (2 pairs).
// 8 warps (256 thr): 4 in M (32px) x 2 in N (32co), rows paired,
// register-double-buffered fragments (R11 core, 127.3us conv).
__global__ __launch_bounds__(256, 1)
void conv_kernel(const float* __restrict__ in,
                 const float* __restrict__ style,
                 const float* __restrict__ mw,
                 const float* __restrict__ mbias,
                 const float* __restrict__ wgt,
                 float* __restrict__ out) {
    extern __shared__ char smem[];
    const uint32_t sb = smem_u32(smem);
    const int tid  = threadIdx.x;
    const int wid  = tid >> 5;
    const int lane = tid & 31;

    const int mwarp = wid & 3;
    const int nwarp = wid >> 2;
    const uint32_t px0 = mwarp * 32;
    const uint32_t co0 = nwarp * 32;

    const uint32_t arow = lane & 15;
    const uint32_t khA  = ((lane >> 4) & 1) * 16;
    const uint32_t brow = (lane & 7) | ((lane >> 1) & 8);
    const uint32_t khB  = ((lane >> 3) & 1) * 16;

    // chunk range: 136 CTAs x 7, 12 CTAs x 6  (1024 = 136*7 + 12*6)
    const int cta = blockIdx.x;
    int c, cnt;
    if (cta < 136) { c = cta * 7;               cnt = 7; }
    else           { c = 952 + (cta - 136) * 6; cnt = 6; }

    float* sOut = (float*)(smem + STAGE_OFF);    // [64co][132px] f32 (reuses stage)
    const int eg = lane >> 2;
    const int et = lane & 3;

    int last_b = -1;

    while (cnt > 0) {
        const int col    = c >> 6;          // 16 columns = b(8) x xh(2)
        const int within = c & 63;
        const int b  = col >> 1;
        const int x0 = (col & 1) * 128;
        const int run = min(cnt, 64 - within);
        const int y0r = within * 4;
        const int npairs = run * 2;

        // ---- stage one raw fp32 input row into the stage buffer ----
        auto stage_async = [&](int iy) {
            if ((unsigned)iy >= 256u) return;
            #pragma unroll
            for (int it = 0; it < 9; it++) {
                int idx = tid + 256 * it;        // 64 ci x 34 chunks = 2176
                if (idx < 2176) {
                    int ci = idx / 34;
                    int cc = idx - ci * 34;
                    int gx0 = x0 - 4 + 4 * cc;
                    uint32_t doff = STAGE_OFF + (uint32_t)(ci * STAGE_W + 4 * cc) * 4u;
                    if ((unsigned)gx0 <= 252u) {
                        cpasync16(sb + doff,
                                  in + (((size_t)(b * CIN + ci)) * HH + iy) * WW + gx0);
                    } else {
                        *(uint4*)(smem + doff) = make_uint4(0, 0, 0, 0);
                    }
                }
            }
        };

        // ---- convert staged fp32 row -> swizzled fp16 ring slot ----
        auto convert_row = [&](int iy) {
            const uint32_t roff = RING_OFF
                + ((uint32_t)((iy + 1 + 768) % 6)) * ROW_STRIDE;
            const bool valid = ((unsigned)iy < 256u);
            const float* st = (const float*)(smem + STAGE_OFF);
            const int g = wid;
            #pragma unroll
            for (int it = 0; it < 5; it++) {
                int px = (it < 4) ? (it * 32 + lane) : (128 + lane);
                if (it == 4 && lane >= 2) break;
                float v[8];
                #pragma unroll
                for (int k = 0; k < 8; k++)
                    v[k] = valid ? st[(g * 8 + k) * STAGE_W + px + 3] : 0.f;
                uint32_t u[4];
                #pragma unroll
                for (int k = 0; k < 4; k++) {
                    __half2 hp = __floats2half2_rn(v[2 * k], v[2 * k + 1]);
                    u[k] = *reinterpret_cast<uint32_t*>(&hp);
                }
                *(uint4*)(smem + roff + sw128((uint32_t)px * 128u + (uint32_t)g * 16u))
                    = make_uint4(u[0], u[1], u[2], u[3]);
            }
        };

        // ---- run prologue: weights (if b changed) + prime rows ----
        if (b != last_b) {
            compute_weights(smem, b, style, mw, mbias, wgt);
            last_b = b;
        }
        #pragma unroll 1
        for (int rnd = 0; rnd < 4; rnd++) {
            stage_async(y0r - 1 + rnd);
            cpcommit();
            cpwait0();
            __syncthreads();
            convert_row(y0r - 1 + rnd);
            __syncthreads();
        }

        // ---- continuous pair loop across the whole run ----
        for (int q = 0; q < npairs; q++) {
            const int y = y0r + 2 * q;
            const bool more = (q < npairs - 1);

            if (more) { stage_async(y + 3); cpcommit(); }

            uint32_t rowA[4];
            #pragma unroll
            for (int j = 0; j < 4; j++)
                rowA[j] = sb + RING_OFF + ((uint32_t)((y + j) % 6)) * ROW_STRIDE;

            float acc[2][2][4][4];
            #pragma unroll
            for (int r = 0; r < 2; r++)
                #pragma unroll
                for (int mf = 0; mf < 2; mf++)
                    #pragma unroll
                    for (int nf = 0; nf < 4; nf++)
                        #pragma unroll
                        for (int cc = 0; cc < 4; cc++) acc[r][mf][nf][cc] = 0.f;

            // double-buffered fragments
            uint32_t afr[2][4][2][4];      // [buf][row][mf][4]
            uint32_t wfr[2][3][4][2];      // [buf][dy][nf][2]

            auto prefetch = [&](int s, int buf) {
                const int kc = s / 3;
                const uint32_t dx = (uint32_t)(s - 3 * kc);
                const uint32_t kb = (uint32_t)kc * 32u;
                #pragma unroll
                for (int dy = 0; dy < 3; dy++) {
                    const uint32_t tap = (uint32_t)(dy * 3) + dx;
                    #pragma unroll
                    for (int g = 0; g < 2; g++) {
                        uint32_t tmp[4];
                        uint32_t o = (tap * 64u + co0 + (uint32_t)g * 16u + brow) * 128u
                                     + kb + khB;
                        ldsm4(tmp, sb + W_OFF + sw128(o));
                        wfr[buf][dy][g * 2][0]     = tmp[0];
                        wfr[buf][dy][g * 2][1]     = tmp[1];
                        wfr[buf][dy][g * 2 + 1][0] = tmp[2];
                        wfr[buf][dy][g * 2 + 1][1] = tmp[3];
                    }
                }
                #pragma unroll
                for (int j = 0; j < 4; j++) {
                    #pragma unroll
                    for (int mf = 0; mf < 2; mf++) {
                        uint32_t o = (px0 + (uint32_t)mf * 16u + arow + dx) * 128u
                                     + kb + khA;
                        ldsm4(afr[buf][j][mf], rowA[j] + sw128(o));
                    }
                }
            };

            prefetch(0, 0);
            #pragma unroll
            for (int s = 0; s < 12; s++) {
                const int buf = s & 1;
                if (s < 11) prefetch(s + 1, buf ^ 1);
                #pragma unroll
                for (int dy = 0; dy < 3; dy++)
                    #pragma unroll
                    for (int r = 0; r < 2; r++)
                        #pragma unroll
                        for (int mf = 0; mf < 2; mf++)
                            #pragma unroll
                            for (int nf = 0; nf < 4; nf++)
                                mma16816(acc[r][mf][nf], afr[buf][r + dy][mf],
                                         wfr[buf][dy][nf][0], wfr[buf][dy][nf][1]);
                // mid-pair: consume staged row y+3, start staging row y+4
                if (s == 5 && more) {
                    cpwait0();
                    __syncthreads();
                    convert_row(y + 3);          // -> slot (y+4)%6 (free)
                    __syncthreads();
                    stage_async(y + 4);
                    cpcommit();
                }
            }

            if (more) {
                cpwait0();
                __syncthreads();
                convert_row(y + 4);              // -> slot (y+5)%6 (free)
            }
            __syncthreads();

            // ---- epilogue: two rows via smem transpose (stage reused) ----
            #pragma unroll
            for (int r = 0; r < 2; r++) {
                #pragma unroll
                for (int mf = 0; mf < 2; mf++) {
                    #pragma unroll
                    for (int nf = 0; nf < 4; nf++) {
                        int px = px0 + mf * 16 + eg;
                        int co = co0 + nf * 8 + 2 * et;
                        sOut[co * 132 + px]           = acc[r][mf][nf][0];
                        sOut[(co + 1) * 132 + px]     = acc[r][mf][nf][1];
                        sOut[co * 132 + px + 8]       = acc[r][mf][nf][2];
                        sOut[(co + 1) * 132 + px + 8] = acc[r][mf][nf][3];
                    }
                }
                __syncthreads();
                #pragma unroll
                for (int k = 0; k < 8; k++) {
                    int idx = tid + 256 * k;        // 2048 float4
                    int co = idx >> 5;
                    int qq = idx & 31;
                    float4 v = *(float4*)&sOut[co * 132 + qq * 4];
                    *(float4*)(out + (((size_t)b * COUT + co) * HH + (y + r)) * WW
                               + x0 + qq * 4) = v;
                }
                __syncthreads();
            }
        }

        c   += run;
        cnt -= run;
    }
}

// ---------------- launch ----------------
extern "C" void kernel_launch(void* const* d_in, const int* in_sizes, int n_in,
                              void* d_out, int out_size) {
    const float* input      = (const float*)d_in[0];
    const float* style      = (const float*)d_in[1];
    const float* weight     = (const float*)d_in[2];
    const float* mod_weight = (const float*)d_in[3];
    const float* mod_bias   = (const float*)d_in[4];
    float* out = (float*)d_out;

    cudaFuncSetAttribute(conv_kernel,
                         cudaFuncAttributeMaxDynamicSharedMemorySize, SMEM_TOTAL);

    conv_kernel<<<NCTA, 256, SMEM_TOTAL>>>(input, style, mod_weight, mod_bias,
                                           weight, out);
}

// round 15
// speedup vs baseline: 1.9403x; 1.9403x over previous
#include <cuda_runtime.h>
#include <cuda_fp16.h>
#include <cstdint>
#include <math.h>

// ---------------- problem constants ----------------
#define BATCH 8
#define CIN   64
#define COUT  64
#define SDIM  512
#define HH    256
#define WW    256
#define TAPS  9

#define CONV_SCALE (1.0f / 24.0f)
#define MOD_SCALE  (0.04419417382415922f)
#define EPSV       (1e-8f)

// ---------------- device scratch ----------------
// demodulated weights fp16: [b][tap][co][ci]
__device__ __align__(16) __half g_wt[BATCH * TAPS * COUT * CIN];

// ---------------- helpers ----------------
__device__ __forceinline__ uint32_t smem_u32(const void* p) {
    uint32_t a;
    asm("{ .reg .u64 t; cvta.to.shared.u64 t, %1; cvt.u32.u64 %0, t; }" : "=r"(a) : "l"(p));
    return a;
}
__device__ __forceinline__ void ldsm4(uint32_t (&r)[4], uint32_t addr) {
    asm volatile("ldmatrix.sync.aligned.m8n8.x4.shared.b16 {%0,%1,%2,%3}, [%4];"
                 : "=r"(r[0]), "=r"(r[1]), "=r"(r[2]), "=r"(r[3]) : "r"(addr));
}
__device__ __forceinline__ void mma16816(float (&c)[4], const uint32_t (&a)[4],
                                         const uint32_t b0, const uint32_t b1) {
    asm volatile(
        "mma.sync.aligned.m16n8k16.row.col.f32.f16.f16.f32 "
        "{%0,%1,%2,%3}, {%4,%5,%6,%7}, {%8,%9}, {%0,%1,%2,%3};"
        : "+f"(c[0]), "+f"(c[1]), "+f"(c[2]), "+f"(c[3])
        : "r"(a[0]), "r"(a[1]), "r"(a[2]), "r"(a[3]), "r"(b0), "r"(b1));
}
__device__ __forceinline__ void cpasync16(uint32_t dst, const void* src) {
    asm volatile("cp.async.cg.shared.global [%0], [%1], 16;" :: "r"(dst), "l"(src) : "memory");
}
__device__ __forceinline__ void cpcommit() { asm volatile("cp.async.commit_group;" ::: "memory"); }
__device__ __forceinline__ void cpwait0()  { asm volatile("cp.async.wait_group 0;" ::: "memory"); }

__device__ __forceinline__ uint32_t sw128(uint32_t o) { return o ^ ((o >> 3) & 0x70u); }

// ---------------- kernel A: cheap fused style + demod -----------------------
// grid (4 co-groups, 8 b), 512 threads. Phase 1 computes all 64 style dots
// once per block (mw L2 traffic 4MB total, was 64MB). Phase 2: one warp per
// co, pure shfl reduction, no smem trees.
__global__ __launch_bounds__(512, 2)
void demod_kernel(const float* __restrict__ style,
                  const float* __restrict__ mw,
                  const float* __restrict__ mb,
                  const float* __restrict__ w) {
    const int cog = blockIdx.x;       // 0..3
    const int b   = blockIdx.y;       // 0..7
    const int tid  = threadIdx.x;
    const int wid  = tid >> 5;
    const int lane = tid & 31;

    __shared__ float sdot[64];

    // phase 1: sdot[ci] = MOD_SCALE * <style_b, mw_ci> + mb[ci]   (8 thr/ci)
    {
        int ci = tid >> 3;
        int j  = tid & 7;
        const float* sp = style + (size_t)b * SDIM;
        const float* wp = mw + (size_t)ci * SDIM;
        float sum = 0.f;
        #pragma unroll 8
        for (int t = 0; t < 64; t++)
            sum += sp[j + 8 * t] * wp[j + 8 * t];
        sum += __shfl_xor_sync(0xFFFFFFFFu, sum, 4);
        sum += __shfl_xor_sync(0xFFFFFFFFu, sum, 2);
        sum += __shfl_xor_sync(0xFFFFFFFFu, sum, 1);
        if (j == 0) sdot[ci] = sum * MOD_SCALE + mb[ci];
    }
    __syncthreads();

    // phase 2: warp w -> co = cog*16 + w
    const int co = cog * 16 + wid;
    const float* wrow = w + (size_t)co * 576;
    float val[18];
    float sumsq = 0.f;
    #pragma unroll
    for (int k = 0; k < 18; k++) {
        int e  = lane + 32 * k;
        int ci = e / 9;
        float v = CONV_SCALE * wrow[e] * sdot[ci];
        val[k] = v;
        sumsq += v * v;
    }
    #pragma unroll
    for (int off = 16; off > 0; off >>= 1)
        sumsq += __shfl_xor_sync(0xFFFFFFFFu, sumsq, off);
    float dm = rsqrtf(sumsq + EPSV);
    #pragma unroll
    for (int k = 0; k < 18; k++) {
        int e   = lane + 32 * k;
        int ci  = e / 9;
        int tap = e - ci * 9;
        g_wt[(((size_t)b * TAPS + tap) * COUT + co) * CIN + ci]
            = __float2half_rn(val[k] * dm);
    }
}

// ---------------- kernel B: persistent conv (R11 core, unchanged) ----------
// Work unit = chunk (xh, y4chunk, b): 128px x 64co x 4 rows (2 pairs).
// 8 warps (256 thr): 4 in M (32px) x 2 in N (32co), rows paired,
// register-double-buffered fragments.
#define W_OFF      0u
#define W_BYTES    73728u
#define RING_OFF   73728u
#define ROW_STRIDE 16640u                        // 130 px x 128B
#define STAGE_OFF  (RING_OFF + 6u * ROW_STRIDE)  // 173568
#define STAGE_W    136                           // fp32 words per ci row
#define SMEM_TOTAL (STAGE_OFF + 64u * STAGE_W * 4u)   // 208384

#define NCTA       148

__global__ __launch_bounds__(256, 1)
void conv_kernel(const float* __restrict__ in, float* __restrict__ out) {
    extern __shared__ char smem[];
    const uint32_t sb = smem_u32(smem);
    const int tid  = threadIdx.x;
    const int wid  = tid >> 5;
    const int lane = tid & 31;

    const int mwarp = wid & 3;
    const int nwarp = wid >> 2;
    const uint32_t px0 = mwarp * 32;
    const uint32_t co0 = nwarp * 32;

    const uint32_t arow = lane & 15;
    const uint32_t khA  = ((lane >> 4) & 1) * 16;
    const uint32_t brow = (lane & 7) | ((lane >> 1) & 8);
    const uint32_t khB  = ((lane >> 3) & 1) * 16;

    // chunk range: 136 CTAs x 7, 12 CTAs x 6  (1024 = 136*7 + 12*6)
    const int cta = blockIdx.x;
    int c, cnt;
    if (cta < 136) { c = cta * 7;               cnt = 7; }
    else           { c = 952 + (cta - 136) * 6; cnt = 6; }

    float* sOut = (float*)(smem + STAGE_OFF);    // [64co][132px] f32 (reuses stage)
    const int eg = lane >> 2;
    const int et = lane & 3;

    int last_b = -1;

    while (cnt > 0) {
        const int col    = c >> 6;          // 16 columns = b(8) x xh(2)
        const int within = c & 63;
        const int b  = col >> 1;
        const int x0 = (col & 1) * 128;
        const int run = min(cnt, 64 - within);
        const int y0r = within * 4;
        const int npairs = run * 2;

        // ---- stage one raw fp32 input row into the stage buffer ----
        auto stage_async = [&](int iy) {
            if ((unsigned)iy >= 256u) return;
            #pragma unroll
            for (int it = 0; it < 9; it++) {
                int idx = tid + 256 * it;        // 64 ci x 34 chunks = 2176
                if (idx < 2176) {
                    int ci = idx / 34;
                    int cc = idx - ci * 34;
                    int gx0 = x0 - 4 + 4 * cc;
                    uint32_t doff = STAGE_OFF + (uint32_t)(ci * STAGE_W + 4 * cc) * 4u;
                    if ((unsigned)gx0 <= 252u) {
                        cpasync16(sb + doff,
                                  in + (((size_t)(b * CIN + ci)) * HH + iy) * WW + gx0);
                    } else {
                        *(uint4*)(smem + doff) = make_uint4(0, 0, 0, 0);
                    }
                }
            }
        };

        // ---- convert staged fp32 row -> swizzled fp16 ring slot ----
        auto convert_row = [&](int iy) {
            const uint32_t roff = RING_OFF
                + ((uint32_t)((iy + 1 + 768) % 6)) * ROW_STRIDE;
            const bool valid = ((unsigned)iy < 256u);
            const float* st = (const float*)(smem + STAGE_OFF);
            const int g = wid;
            #pragma unroll
            for (int it = 0; it < 5; it++) {
                int px = (it < 4) ? (it * 32 + lane) : (128 + lane);
                if (it == 4 && lane >= 2) break;
                float v[8];
                #pragma unroll
                for (int k = 0; k < 8; k++)
                    v[k] = valid ? st[(g * 8 + k) * STAGE_W + px + 3] : 0.f;
                uint32_t u[4];
                #pragma unroll
                for (int k = 0; k < 4; k++) {
                    __half2 hp = __floats2half2_rn(v[2 * k], v[2 * k + 1]);
                    u[k] = *reinterpret_cast<uint32_t*>(&hp);
                }
                *(uint4*)(smem + roff + sw128((uint32_t)px * 128u + (uint32_t)g * 16u))
                    = make_uint4(u[0], u[1], u[2], u[3]);
            }
        };

        // ---- run prologue: W (if b changed) + prime rows y0r-1..y0r+2 ----
        if (b != last_b) {
            const uint4* ws = ((const uint4*)g_wt) + (size_t)b * 4608;
            for (int j = tid; j < 4608; j += 256) {
                uint32_t o = (uint32_t)j << 4;
                cpasync16(sb + W_OFF + sw128(o), ws + j);
            }
            cpcommit();
            last_b = b;
        }
        #pragma unroll 1
        for (int rnd = 0; rnd < 4; rnd++) {
            stage_async(y0r - 1 + rnd);
            cpcommit();
            cpwait0();
            __syncthreads();
            convert_row(y0r - 1 + rnd);
            __syncthreads();
        }

        // ---- continuous pair loop across the whole run ----
        for (int q = 0; q < npairs; q++) {
            const int y = y0r + 2 * q;
            const bool more = (q < npairs - 1);

            if (more) { stage_async(y + 3); cpcommit(); }

            uint32_t rowA[4];
            #pragma unroll
            for (int j = 0; j < 4; j++)
                rowA[j] = sb + RING_OFF + ((uint32_t)((y + j) % 6)) * ROW_STRIDE;

            float acc[2][2][4][4];
            #pragma unroll
            for (int r = 0; r < 2; r++)
                #pragma unroll
                for (int mf = 0; mf < 2; mf++)
                    #pragma unroll
                    for (int nf = 0; nf < 4; nf++)
                        #pragma unroll
                        for (int cc = 0; cc < 4; cc++) acc[r][mf][nf][cc] = 0.f;

            // double-buffered fragments
            uint32_t afr[2][4][2][4];      // [buf][row][mf][4]
            uint32_t wfr[2][3][4][2];      // [buf][dy][nf][2]

            auto prefetch = [&](int s, int buf) {
                const int kc = s / 3;
                const uint32_t dx = (uint32_t)(s - 3 * kc);
                const uint32_t kb = (uint32_t)kc * 32u;
                #pragma unroll
                for (int dy = 0; dy < 3; dy++) {
                    const uint32_t tap = (uint32_t)(dy * 3) + dx;
                    #pragma unroll
                    for (int g = 0; g < 2; g++) {
                        uint32_t tmp[4];
                        uint32_t o = (tap * 64u + co0 + (uint32_t)g * 16u + brow) * 128u
                                     + kb + khB;
                        ldsm4(tmp, sb + W_OFF + sw128(o));
                        wfr[buf][dy][g * 2][0]     = tmp[0];
                        wfr[buf][dy][g * 2][1]     = tmp[1];
                        wfr[buf][dy][g * 2 + 1][0] = tmp[2];
                        wfr[buf][dy][g * 2 + 1][1] = tmp[3];
                    }
                }
                #pragma unroll
                for (int j = 0; j < 4; j++) {
                    #pragma unroll
                    for (int mf = 0; mf < 2; mf++) {
                        uint32_t o = (px0 + (uint32_t)mf * 16u + arow + dx) * 128u
                                     + kb + khA;
                        ldsm4(afr[buf][j][mf], rowA[j] + sw128(o));
                    }
                }
            };

            prefetch(0, 0);
            #pragma unroll
            for (int s = 0; s < 12; s++) {
                const int buf = s & 1;
                if (s < 11) prefetch(s + 1, buf ^ 1);
                #pragma unroll
                for (int dy = 0; dy < 3; dy++)
                    #pragma unroll
                    for (int r = 0; r < 2; r++)
                        #pragma unroll
                        for (int mf = 0; mf < 2; mf++)
                            #pragma unroll
                            for (int nf = 0; nf < 4; nf++)
                                mma16816(acc[r][mf][nf], afr[buf][r + dy][mf],
                                         wfr[buf][dy][nf][0], wfr[buf][dy][nf][1]);
                // mid-pair: consume staged row y+3, start staging row y+4
                if (s == 5 && more) {
                    cpwait0();
                    __syncthreads();
                    convert_row(y + 3);          // -> slot (y+4)%6 (free)
                    __syncthreads();
                    stage_async(y + 4);
                    cpcommit();
                }
            }

            if (more) {
                cpwait0();
                __syncthreads();
                convert_row(y + 4);              // -> slot (y+5)%6 (free)
            }
            __syncthreads();

            // ---- epilogue: two rows via smem transpose (stage reused) ----
            #pragma unroll
            for (int r = 0; r < 2; r++) {
                #pragma unroll
                for (int mf = 0; mf < 2; mf++) {
                    #pragma unroll
                    for (int nf = 0; nf < 4; nf++) {
                        int px = px0 + mf * 16 + eg;
                        int co = co0 + nf * 8 + 2 * et;
                        sOut[co * 132 + px]           = acc[r][mf][nf][0];
                        sOut[(co + 1) * 132 + px]     = acc[r][mf][nf][1];
                        sOut[co * 132 + px + 8]       = acc[r][mf][nf][2];
                        sOut[(co + 1) * 132 + px + 8] = acc[r][mf][nf][3];
                    }
                }
                __syncthreads();
                #pragma unroll
                for (int k = 0; k < 8; k++) {
                    int idx = tid + 256 * k;        // 2048 float4
                    int co = idx >> 5;
                    int qq = idx & 31;
                    float4 v = *(float4*)&sOut[co * 132 + qq * 4];
                    *(float4*)(out + (((size_t)b * COUT + co) * HH + (y + r)) * WW
                               + x0 + qq * 4) = v;
                }
                __syncthreads();
            }
        }

        c   += run;
        cnt -= run;
    }
}

// ---------------- launch ----------------
extern "C" void kernel_launch(void* const* d_in, const int* in_sizes, int n_in,
                              void* d_out, int out_size) {
    const float* input      = (const float*)d_in[0];
    const float* style      = (const float*)d_in[1];
    const float* weight     = (const float*)d_in[2];
    const float* mod_weight = (const float*)d_in[3];
    const float* mod_bias   = (const float*)d_in[4];
    float* out = (float*)d_out;

    cudaFuncSetAttribute(conv_kernel,
                         cudaFuncAttributeMaxDynamicSharedMemorySize, SMEM_TOTAL);

    demod_kernel<<<dim3(4, BATCH), 512>>>(style, mod_weight, mod_bias, weight);
    conv_kernel<<<NCTA, 256, SMEM_TOTAL>>>(input, out);
}

// round 16
// speedup vs baseline: 2.0966x; 1.0806x over previous
#include <cuda_runtime.h>
#include <cuda_fp16.h>
#include <cstdint>
#include <math.h>

// ---------------- problem constants ----------------
#define BATCH 8
#define CIN   64
#define COUT  64
#define SDIM  512
#define HH    256
#define WW    256
#define TAPS  9

#define CONV_SCALE (1.0f / 24.0f)
#define MOD_SCALE  (0.04419417382415922f)
#define EPSV       (1e-8f)

// ---------------- device scratch ----------------
// x-transformed demodulated weights fp16: [b][dy*4+t][co][ci]  (12 tiles/b)
__device__ __align__(16) __half g_wt[BATCH * 12 * COUT * CIN];

// ---------------- helpers ----------------
__device__ __forceinline__ uint32_t smem_u32(const void* p) {
    uint32_t a;
    asm("{ .reg .u64 t; cvta.to.shared.u64 t, %1; cvt.u32.u64 %0, t; }" : "=r"(a) : "l"(p));
    return a;
}
__device__ __forceinline__ void ldsm4(uint32_t (&r)[4], uint32_t addr) {
    asm volatile("ldmatrix.sync.aligned.m8n8.x4.shared.b16 {%0,%1,%2,%3}, [%4];"
                 : "=r"(r[0]), "=r"(r[1]), "=r"(r[2]), "=r"(r[3]) : "r"(addr));
}
__device__ __forceinline__ void mma16816(float (&c)[4], const uint32_t (&a)[4],
                                         const uint32_t b0, const uint32_t b1) {
    asm volatile(
        "mma.sync.aligned.m16n8k16.row.col.f32.f16.f16.f32 "
        "{%0,%1,%2,%3}, {%4,%5,%6,%7}, {%8,%9}, {%0,%1,%2,%3};"
        : "+f"(c[0]), "+f"(c[1]), "+f"(c[2]), "+f"(c[3])
        : "r"(a[0]), "r"(a[1]), "r"(a[2]), "r"(a[3]), "r"(b0), "r"(b1));
}
__device__ __forceinline__ uint32_t hadd2u(uint32_t a, uint32_t b) {
    uint32_t d;
    asm("add.f16x2 %0, %1, %2;" : "=r"(d) : "r"(a), "r"(b));
    return d;
}
__device__ __forceinline__ uint32_t hsub2u(uint32_t a, uint32_t b) {
    uint32_t d;
    asm("sub.f16x2 %0, %1, %2;" : "=r"(d) : "r"(a), "r"(b));
    return d;
}
__device__ __forceinline__ void cpasync16(uint32_t dst, const void* src) {
    asm volatile("cp.async.cg.shared.global [%0], [%1], 16;" :: "r"(dst), "l"(src) : "memory");
}
__device__ __forceinline__ void cpcommit() { asm volatile("cp.async.commit_group;" ::: "memory"); }
__device__ __forceinline__ void cpwait0()  { asm volatile("cp.async.wait_group 0;" ::: "memory"); }

__device__ __forceinline__ uint32_t sw128(uint32_t o) { return o ^ ((o >> 3) & 0x70u); }

// ---------------- kernel A: style + demod + x-Winograd W transform ---------
// grid (4 co-groups, 8 b), 512 threads; warp = one co.
__global__ __launch_bounds__(512, 2)
void demod_kernel(const float* __restrict__ style,
                  const float* __restrict__ mw,
                  const float* __restrict__ mb,
                  const float* __restrict__ w) {
    const int cog = blockIdx.x;
    const int b   = blockIdx.y;
    const int tid  = threadIdx.x;
    const int wid  = tid >> 5;
    const int lane = tid & 31;

    __shared__ float sdot[64];

    // phase 1: sdot[ci] = MOD_SCALE * <style_b, mw_ci> + mb[ci]   (8 thr/ci)
    {
        int ci = tid >> 3;
        int j  = tid & 7;
        const float* sp = style + (size_t)b * SDIM;
        const float* wp = mw + (size_t)ci * SDIM;
        float sum = 0.f;
        #pragma unroll 8
        for (int t = 0; t < 64; t++)
            sum += sp[j + 8 * t] * wp[j + 8 * t];
        sum += __shfl_xor_sync(0xFFFFFFFFu, sum, 4);
        sum += __shfl_xor_sync(0xFFFFFFFFu, sum, 2);
        sum += __shfl_xor_sync(0xFFFFFFFFu, sum, 1);
        if (j == 0) sdot[ci] = sum * MOD_SCALE + mb[ci];
    }
    __syncthreads();

    // phase 2: warp -> co; lane handles ci = lane and lane+32 (all 9 taps)
    const int co = cog * 16 + wid;
    const float* wrow = w + (size_t)co * 576;
    float v[2][9];
    float sumsq = 0.f;
    #pragma unroll
    for (int cih = 0; cih < 2; cih++) {
        int ci = lane + 32 * cih;
        float sd = sdot[ci];
        #pragma unroll
        for (int tap = 0; tap < 9; tap++) {
            float x = CONV_SCALE * wrow[ci * 9 + tap] * sd;
            v[cih][tap] = x;
            sumsq += x * x;
        }
    }
    #pragma unroll
    for (int off = 16; off > 0; off >>= 1)
        sumsq += __shfl_xor_sync(0xFFFFFFFFu, sumsq, off);
    float dm = rsqrtf(sumsq + EPSV);

    // x-Winograd transform per (ci, dy): t = {w0, (w0+w1+w2)/2, (w0-w1+w2)/2, w2}
    #pragma unroll
    for (int cih = 0; cih < 2; cih++) {
        int ci = lane + 32 * cih;
        #pragma unroll
        for (int dy = 0; dy < 3; dy++) {
            float w0 = v[cih][dy * 3 + 0] * dm;
            float w1 = v[cih][dy * 3 + 1] * dm;
            float w2 = v[cih][dy * 3 + 2] * dm;
            float t0 = w0;
            float t1 = (w0 + w1 + w2) * 0.5f;
            float t2 = (w0 - w1 + w2) * 0.5f;
            float t3 = w2;
            size_t base = (((size_t)b * 12 + dy * 4) * COUT + co) * CIN + ci;
            g_wt[base]                      = __float2half_rn(t0);
            g_wt[base + (size_t)COUT * CIN]     = __float2half_rn(t1);
            g_wt[base + (size_t)2 * COUT * CIN] = __float2half_rn(t2);
            g_wt[base + (size_t)3 * COUT * CIN] = __float2half_rn(t3);
        }
    }
}

// ---------------- kernel B: persistent Winograd-x conv ---------------------
// Work unit = chunk (xh, y4chunk, b): 128 out px (= 64 tiles) x 64co x 4 rows.
// 8 warps (256 thr): 4 in M (16 tiles) x 2 in N (32co), rows paired.
// Ring: 5 slots, polyphase fp16: O plane (in[x0-1+2m]) + E plane (in[x0+2m]),
// m = 0..64, 128B rows. A-transform = fragment-wise f16x2 add/sub.
#define W_OFF       0u
#define W_BYTES     98304u                        // 12 x 64 x 128B
#define RING_OFF    98304u
#define SLOT_STRIDE 16640u                        // 2 planes x 65 x 128B
#define PLANE_E     8320u
#define STAGE_OFF   (RING_OFF + 5u * SLOT_STRIDE) // 181504
#define STAGE_W     136
#define SMEM_TOTAL  (STAGE_OFF + 64u * STAGE_W * 4u)   // 216320

#define NCTA        148

__global__ __launch_bounds__(256, 1)
void conv_kernel(const float* __restrict__ in, float* __restrict__ out) {
    extern __shared__ char smem[];
    const uint32_t sb = smem_u32(smem);
    const int tid  = threadIdx.x;
    const int wid  = tid >> 5;
    const int lane = tid & 31;

    const int mwarp = wid & 3;            // 4 x 16 tiles
    const int nwarp = wid >> 2;           // 2 x 32 co
    const uint32_t mt  = mwarp * 16;
    const uint32_t co0 = nwarp * 32;

    const uint32_t arow = lane & 15;
    const uint32_t khA  = ((lane >> 4) & 1) * 16;
    const uint32_t brow = (lane & 7) | ((lane >> 1) & 8);
    const uint32_t khB  = ((lane >> 3) & 1) * 16;

    // chunk range: 136 CTAs x 7, 12 CTAs x 6  (1024 = 136*7 + 12*6)
    const int cta = blockIdx.x;
    int c, cnt;
    if (cta < 136) { c = cta * 7;               cnt = 7; }
    else           { c = 952 + (cta - 136) * 6; cnt = 6; }

    float* sOut = (float*)(smem + STAGE_OFF);    // [64co][132px] f32 (reuses stage)
    const int eg = lane >> 2;                    // fragment row 0..7
    const int tq = lane & 3;                     // fragment col pair

    int last_b = -1;

    while (cnt > 0) {
        const int col    = c >> 6;          // 16 columns = b(8) x xh(2)
        const int within = c & 63;
        const int b  = col >> 1;
        const int x0 = (col & 1) * 128;
        const int run = min(cnt, 64 - within);
        const int y0r = within * 4;
        const int npairs = run * 2;

        // ---- stage one raw fp32 input row (words: gx = x0-4+w) ----
        auto stage_async = [&](int iy) {
            if ((unsigned)iy >= 256u) return;
            #pragma unroll
            for (int it = 0; it < 9; it++) {
                int idx = tid + 256 * it;        // 64 ci x 34 chunks = 2176
                if (idx < 2176) {
                    int ci = idx / 34;
                    int cc = idx - ci * 34;
                    int gx0 = x0 - 4 + 4 * cc;
                    uint32_t doff = STAGE_OFF + (uint32_t)(ci * STAGE_W + 4 * cc) * 4u;
                    if ((unsigned)gx0 <= 252u) {
                        cpasync16(sb + doff,
                                  in + (((size_t)(b * CIN + ci)) * HH + iy) * WW + gx0);
                    } else {
                        *(uint4*)(smem + doff) = make_uint4(0, 0, 0, 0);
                    }
                }
            }
        };

        // ---- convert staged fp32 row -> polyphase fp16 ring slot ----
        // O[m] = in[x0-1+2m] (word 2m+3), E[m] = in[x0+2m] (word 2m+4), m=0..64
        auto convert_row = [&](int iy) {
            const uint32_t roff = RING_OFF
                + ((uint32_t)((iy + 1) % 5)) * SLOT_STRIDE;
            const bool valid = ((unsigned)iy < 256u);
            const float* st = (const float*)(smem + STAGE_OFF);
            const int g = wid;                   // ci group 8g..8g+7
            #pragma unroll
            for (int h = 0; h < 2; h++) {        // 0 = O plane, 1 = E plane
                #pragma unroll
                for (int it = 0; it < 3; it++) {
                    int m = it * 32 + lane;
                    if (it == 2 && lane >= 1) break;   // m <= 64
                    int word = 2 * m + 3 + h;
                    float vv[8];
                    #pragma unroll
                    for (int k = 0; k < 8; k++)
                        vv[k] = valid ? st[(g * 8 + k) * STAGE_W + word] : 0.f;
                    uint32_t u[4];
                    #pragma unroll
                    for (int k = 0; k < 4; k++) {
                        __half2 hp = __floats2half2_rn(vv[2 * k], vv[2 * k + 1]);
                        u[k] = *reinterpret_cast<uint32_t*>(&hp);
                    }
                    *(uint4*)(smem + roff + (uint32_t)h * PLANE_E
                              + sw128((uint32_t)m * 128u + (uint32_t)g * 16u))
                        = make_uint4(u[0], u[1], u[2], u[3]);
                }
            }
        };

        // ---- run prologue: W (if b changed) + prime rows y0r-1..y0r+2 ----
        if (b != last_b) {
            const uint4* ws = ((const uint4*)g_wt) + (size_t)b * 6144;
            for (int j = tid; j < 6144; j += 256) {
                uint32_t o = (uint32_t)j << 4;
                cpasync16(sb + W_OFF + sw128(o), ws + j);
            }
            cpcommit();
            last_b = b;
        }
        #pragma unroll 1
        for (int rnd = 0; rnd < 4; rnd++) {
            stage_async(y0r - 1 + rnd);
            cpcommit();
            cpwait0();
            __syncthreads();
            convert_row(y0r - 1 + rnd);
            __syncthreads();
        }

        // ---- continuous pair loop across the whole run ----
        for (int q = 0; q < npairs; q++) {
            const int y = y0r + 2 * q;
            const bool more = (q < npairs - 1);

            if (more) { stage_async(y + 3); cpcommit(); }

            uint32_t slotb[4];
            #pragma unroll
            for (int j = 0; j < 4; j++)       // input row iy = y-1+j -> slot (y+j)%5
                slotb[j] = sb + RING_OFF + ((uint32_t)((y + j) % 5)) * SLOT_STRIDE;

            float acc[4][2][4][4];            // [t][r][nf][c]
            #pragma unroll
            for (int t = 0; t < 4; t++)
                #pragma unroll
                for (int r = 0; r < 2; r++)
                    #pragma unroll
                    for (int nf = 0; nf < 4; nf++)
                        #pragma unroll
                        for (int cc = 0; cc < 4; cc++) acc[t][r][nf][cc] = 0.f;

            #pragma unroll
            for (int kc = 0; kc < 4; kc++) {
                const uint32_t kb = (uint32_t)kc * 32u;

                // A: load polyphase fragments, transform to 4 t-point frags
                uint32_t at[4][4][4];         // [row j][t][reg]
                #pragma unroll
                for (int j = 0; j < 4; j++) {
                    uint32_t O[4], E[4], Op[4], Ep[4];
                    uint32_t ao = sw128((mt + arow) * 128u + kb + khA);
                    uint32_t a1 = sw128((mt + 1 + arow) * 128u + kb + khA);
                    ldsm4(O,  slotb[j] + ao);
                    ldsm4(E,  slotb[j] + PLANE_E + ao);
                    ldsm4(Op, slotb[j] + a1);
                    ldsm4(Ep, slotb[j] + PLANE_E + a1);
                    #pragma unroll
                    for (int i = 0; i < 4; i++) {
                        at[j][0][i] = hsub2u(O[i], Op[i]);   // d0 - d2
                        at[j][1][i] = hadd2u(E[i], Op[i]);   // d1 + d2
                        at[j][2][i] = hsub2u(Op[i], E[i]);   // d2 - d1
                        at[j][3][i] = hsub2u(E[i], Ep[i]);   // d1 - d3
                    }
                }

                #pragma unroll
                for (int dy = 0; dy < 3; dy++) {
                    #pragma unroll
                    for (int t = 0; t < 4; t++) {
                        const uint32_t tt = (uint32_t)(dy * 4 + t);
                        uint32_t wa[4], wb[4];
                        ldsm4(wa, sb + W_OFF
                              + sw128((tt * 64u + co0 + brow) * 128u + kb + khB));
                        ldsm4(wb, sb + W_OFF
                              + sw128((tt * 64u + co0 + 16u + brow) * 128u + kb + khB));
                        #pragma unroll
                        for (int r = 0; r < 2; r++) {
                            mma16816(acc[t][r][0], at[r + dy][t], wa[0], wa[1]);
                            mma16816(acc[t][r][1], at[r + dy][t], wa[2], wa[3]);
                            mma16816(acc[t][r][2], at[r + dy][t], wb[0], wb[1]);
                            mma16816(acc[t][r][3], at[r + dy][t], wb[2], wb[3]);
                        }
                    }
                }

                // mid-pair: consume staged row y+3, start staging row y+4
                if (kc == 1 && more) {
                    cpwait0();
                    __syncthreads();
                    convert_row(y + 3);          // -> slot (y+4)%5 (free)
                    __syncthreads();
                    stage_async(y + 4);
                    cpcommit();
                }
            }

            if (more) {
                cpwait0();
                __syncthreads();
                convert_row(y + 4);              // -> slot (y+5)%5 = (y)%5 (now free)
            }
            __syncthreads();

            // ---- epilogue: inverse transform + smem transpose + stores ----
            #pragma unroll
            for (int r = 0; r < 2; r++) {
                #pragma unroll
                for (int nf = 0; nf < 4; nf++) {
                    #pragma unroll
                    for (int cc = 0; cc < 4; cc++) {
                        int p  = cc & 1;
                        int g2 = cc >> 1;
                        int tile = mt + eg + g2 * 8;
                        int co   = co0 + nf * 8 + 2 * tq + p;
                        float oe = acc[0][r][nf][cc] + acc[1][r][nf][cc]
                                 + acc[2][r][nf][cc];
                        float oo = acc[1][r][nf][cc] - acc[2][r][nf][cc]
                                 - acc[3][r][nf][cc];
                        sOut[co * 132 + 2 * tile]     = oe;
                        sOut[co * 132 + 2 * tile + 1] = oo;
                    }
                }
                __syncthreads();
                #pragma unroll
                for (int k = 0; k < 8; k++) {
                    int idx = tid + 256 * k;        // 2048 float4
                    int co = idx >> 5;
                    int qq = idx & 31;
                    float4 vv = *(float4*)&sOut[co * 132 + qq * 4];
                    *(float4*)(out + (((size_t)b * COUT + co) * HH + (y + r)) * WW
                               + x0 + qq * 4) = vv;
                }
                __syncthreads();
            }
        }

        c   += run;
        cnt -= run;
    }
}

// ---------------- launch ----------------
extern "C" void kernel_launch(void* const* d_in, const int* in_sizes, int n_in,
                              void* d_out, int out_size) {
    const float* input      = (const float*)d_in[0];
    const float* style      = (const float*)d_in[1];
    const float* weight     = (const float*)d_in[2];
    const float* mod_weight = (const float*)d_in[3];
    const float* mod_bias   = (const float*)d_in[4];
    float* out = (float*)d_out;

    cudaFuncSetAttribute(conv_kernel,
                         cudaFuncAttributeMaxDynamicSharedMemorySize, SMEM_TOTAL);

    demod_kernel<<<dim3(4, BATCH), 512>>>(style, mod_weight, mod_bias, weight);
    conv_kernel<<<NCTA, 256, SMEM_TOTAL>>>(input, out);
}